// round 1
// baseline (speedup 1.0000x reference)
#include <cuda_runtime.h>

#define LDIM 16
#define CDIM 16
#define WID 128
#define BATCH 2048
#define NSTEPS 8
#define NT 17            // distinct t values: 1 - k/16, k=0..16
#define SPB 16           // samples per block
#define NTH 128
#define LOG2PI_F 1.8378770664093453f

// Precomputed per-t tables (setup kernel fills these every launch)
__device__ float g_Qt[NT][WID][WID];        // Qt[m][j][i] = Q_m[i][j]
__device__ float g_g0[NT][WID], g_be0[NT][WID];
__device__ float g_g1[NT][WID], g_be1[NT][WID];
__device__ float g_g2[NT][LDIM], g_be2[NT][LDIM];

__device__ __forceinline__ float sigmoidf_(float x) {
    return __fdividef(1.0f, 1.0f + __expf(-x));
}
__device__ __forceinline__ float tanhf_(float x) {
    // robust for |x| large: exp->inf gives 1, exp->0 gives -1
    return 1.0f - __fdividef(2.0f, __expf(2.0f * x) + 1.0f);
}

// ---------------------------------------------------------------------------
// Setup: per t-value gates, effective biases, and divergence matrix Q(t).
// Q[i,j] = g1[i] * W1_1[i,j] * g0[j] * sum_k W1_0[j,k] * g2[k] * W1_2[k,i]
// grid = NT blocks, 128 threads; thread = output index i
// ---------------------------------------------------------------------------
__global__ void prep_kernel(
    const float* __restrict__ W1_0, const float* __restrict__ b1_0,
    const float* __restrict__ W2_0, const float* __restrict__ b2_0,
    const float* __restrict__ W3_0,
    const float* __restrict__ W1_1, const float* __restrict__ b1_1,
    const float* __restrict__ W2_1, const float* __restrict__ b2_1,
    const float* __restrict__ W3_1,
    const float* __restrict__ W1_2, const float* __restrict__ b1_2,
    const float* __restrict__ W2_2, const float* __restrict__ b2_2,
    const float* __restrict__ W3_2)
{
    const int m = blockIdx.x;
    const int i = threadIdx.x;
    const float t = 1.0f - 0.0625f * (float)m;

    __shared__ float sg0[WID], sg1[WID], sg2[LDIM];

    {
        float g = sigmoidf_(W2_0[i] * t + b2_0[i]);
        sg0[i] = g;
        g_g0[m][i] = g;
        g_be0[m][i] = g * b1_0[i] + t * W3_0[i];

        float h = sigmoidf_(W2_1[i] * t + b2_1[i]);
        sg1[i] = h;
        g_g1[m][i] = h;
        g_be1[m][i] = h * b1_1[i] + t * W3_1[i];
    }
    if (i < LDIM) {
        float g = sigmoidf_(W2_2[i] * t + b2_2[i]);
        sg2[i] = g;
        g_g2[m][i] = g;
        g_be2[m][i] = g * b1_2[i] + t * W3_2[i];
    }
    __syncthreads();

    float a[LDIM];
#pragma unroll
    for (int k = 0; k < LDIM; k++) a[k] = sg2[k] * W1_2[k * WID + i];
    const float g1i = sg1[i];

    for (int j = 0; j < WID; j++) {
        float p = 0.0f;
#pragma unroll
        for (int k = 0; k < LDIM; k++) p += W1_0[j * (LDIM + CDIM) + k] * a[k];
        g_Qt[m][j][i] = g1i * W1_1[i * WID + j] * (sg0[j] * p);
    }
}

// ---------------------------------------------------------------------------
// Main persistent kernel: each block integrates 16 samples through all
// 8 RK4 steps. Weights in smem; Q streamed from L2.
// Activation layout [q][neuron*4 + c] with sample s = 4q + c
// => conflict-free float4 stores and broadcast float4 loads.
// ---------------------------------------------------------------------------
struct SM {
    float Wt0[LDIM + CDIM][WID];   // Wt0[j][i] = W1_0[i][j]
    float Wt1[WID][WID];           // Wt1[j][i] = W1_1[i][j]
    float Wt2[WID][LDIM];          // Wt2[i][k] = W1_2[k][i]
    float x [4][(LDIM + CDIM) * 4];
    float h1[4][WID * 4];
    float d1[4][WID * 4];
    float h2[4][WID * 4];
    float fb[LDIM][SPB];
    float yb[LDIM][SPB];
    float ya[LDIM][SPB];
    float dlp[SPB];
    float wred[4][SPB];
};

__global__ void __launch_bounds__(NTH, 1)
cnf_kernel(const float* __restrict__ z, const float* __restrict__ cond,
           const float* __restrict__ W1_0, const float* __restrict__ W1_1,
           const float* __restrict__ W1_2, float* __restrict__ out)
{
    extern __shared__ float smraw[];
    SM* sm = reinterpret_cast<SM*>(smraw);
    const int tid  = threadIdx.x;
    const int lane = tid & 31;
    const int wrp  = tid >> 5;
    const int s0   = blockIdx.x * SPB;

    // --- load transposed weights into smem (one-time cost) ---
    for (int idx = tid; idx < WID * (LDIM + CDIM); idx += NTH) {
        int i = idx >> 5, j = idx & 31;
        sm->Wt0[j][i] = W1_0[idx];
    }
    for (int idx = tid; idx < WID * WID; idx += NTH) {
        int i = idx >> 7, j = idx & 127;
        sm->Wt1[j][i] = W1_1[idx];
    }
    for (int idx = tid; idx < LDIM * WID; idx += NTH) {
        int k = idx >> 7, i = idx & 127;
        sm->Wt2[i][k] = W1_2[idx];
    }
    // --- per-sample state ---
    for (int idx = tid; idx < SPB * LDIM; idx += NTH) {
        int s = idx >> 4, l = idx & 15;
        sm->yb[l][s] = z[(s0 + s) * LDIM + l];
        sm->ya[l][s] = 0.0f;
    }
    for (int idx = tid; idx < SPB * CDIM; idx += NTH) {
        int s = idx >> 4, c = idx & 15;
        sm->x[s >> 2][(LDIM + c) * 4 + (s & 3)] = cond[(s0 + s) * CDIM + c];
    }
    if (tid < SPB) sm->dlp[tid] = 0.0f;
    __syncthreads();

    const float dt  = -0.125f;
    const float dt6 = dt * (1.0f / 6.0f);

    for (int step = 0; step < NSTEPS; step++) {
        for (int st = 0; st < 4; st++) {
            const int   m    = 2 * step + ((st == 0) ? 0 : ((st == 3) ? 2 : 1));
            const float coef = (st == 0) ? 0.0f : ((st == 3) ? dt : 0.5f * dt);
            const float wst  = (st == 1 || st == 2) ? 2.0f : 1.0f;

            // stage input y-part: y + coef * f_prev
            for (int idx = tid; idx < LDIM * SPB; idx += NTH) {
                int j = idx >> 4, s = idx & 15;
                float v = sm->yb[j][s];
                if (st) v += coef * sm->fb[j][s];
                sm->x[s >> 2][j * 4 + (s & 3)] = v;
            }
            __syncthreads();

            // ----- layer 0: 32 -> 128 -----
            float acc[SPB];
#pragma unroll
            for (int s = 0; s < SPB; s++) acc[s] = 0.0f;
#pragma unroll 4
            for (int j = 0; j < LDIM + CDIM; j++) {
                float w = sm->Wt0[j][tid];
#pragma unroll
                for (int q = 0; q < 4; q++) {
                    float4 xv = *reinterpret_cast<const float4*>(&sm->x[q][j * 4]);
                    acc[q * 4 + 0] += w * xv.x;
                    acc[q * 4 + 1] += w * xv.y;
                    acc[q * 4 + 2] += w * xv.z;
                    acc[q * 4 + 3] += w * xv.w;
                }
            }
            {
                const float g = g_g0[m][tid], be = g_be0[m][tid];
#pragma unroll
                for (int q = 0; q < 4; q++) {
                    float4 hv, dv;
                    float h;
                    h = tanhf_(g * acc[q * 4 + 0] + be); hv.x = h; dv.x = 1.0f - h * h;
                    h = tanhf_(g * acc[q * 4 + 1] + be); hv.y = h; dv.y = 1.0f - h * h;
                    h = tanhf_(g * acc[q * 4 + 2] + be); hv.z = h; dv.z = 1.0f - h * h;
                    h = tanhf_(g * acc[q * 4 + 3] + be); hv.w = h; dv.w = 1.0f - h * h;
                    *reinterpret_cast<float4*>(&sm->h1[q][tid * 4]) = hv;
                    *reinterpret_cast<float4*>(&sm->d1[q][tid * 4]) = dv;
                }
            }
            __syncthreads();

            // ----- fused layer 1 (128x128) + divergence matvec u = Q d1 -----
            float acc2[SPB];
#pragma unroll
            for (int s = 0; s < SPB; s++) { acc[s] = 0.0f; acc2[s] = 0.0f; }
            const float* qcol = &g_Qt[m][0][tid];
#pragma unroll 4
            for (int j = 0; j < WID; j++) {
                float w  = sm->Wt1[j][tid];
                float qv = __ldg(qcol + j * WID);
#pragma unroll
                for (int q = 0; q < 4; q++) {
                    float4 hv = *reinterpret_cast<const float4*>(&sm->h1[q][j * 4]);
                    float4 dv = *reinterpret_cast<const float4*>(&sm->d1[q][j * 4]);
                    acc [q * 4 + 0] += w  * hv.x;
                    acc [q * 4 + 1] += w  * hv.y;
                    acc [q * 4 + 2] += w  * hv.z;
                    acc [q * 4 + 3] += w  * hv.w;
                    acc2[q * 4 + 0] += qv * dv.x;
                    acc2[q * 4 + 1] += qv * dv.y;
                    acc2[q * 4 + 2] += qv * dv.z;
                    acc2[q * 4 + 3] += qv * dv.w;
                }
            }
            {
                const float g = g_g1[m][tid], be = g_be1[m][tid];
#pragma unroll
                for (int q = 0; q < 4; q++) {
                    float4 hv;
                    float h;
                    h = tanhf_(g * acc[q * 4 + 0] + be); hv.x = h; acc2[q * 4 + 0] *= (1.0f - h * h);
                    h = tanhf_(g * acc[q * 4 + 1] + be); hv.y = h; acc2[q * 4 + 1] *= (1.0f - h * h);
                    h = tanhf_(g * acc[q * 4 + 2] + be); hv.z = h; acc2[q * 4 + 2] *= (1.0f - h * h);
                    h = tanhf_(g * acc[q * 4 + 3] + be); hv.w = h; acc2[q * 4 + 3] *= (1.0f - h * h);
                    *reinterpret_cast<float4*>(&sm->h2[q][tid * 4]) = hv;
                }
                // divergence: reduce d2[i]*u[i] over i (lanes, then warps)
#pragma unroll
                for (int s = 0; s < SPB; s++) {
                    float v = acc2[s];
                    v += __shfl_xor_sync(0xffffffffu, v, 16);
                    v += __shfl_xor_sync(0xffffffffu, v, 8);
                    v += __shfl_xor_sync(0xffffffffu, v, 4);
                    v += __shfl_xor_sync(0xffffffffu, v, 2);
                    v += __shfl_xor_sync(0xffffffffu, v, 1);
                    if (lane == 0) sm->wred[wrp][s] = v;
                }
            }
            __syncthreads();

            // ----- layer 2: 128 -> 16, RK4 accumulation -----
            {
                const int k  = tid & 15;
                const int sg = tid >> 4;
#pragma unroll
                for (int r = 0; r < 2; r++) {
                    const int s = sg * 2 + r;
                    float fa = 0.0f;
#pragma unroll 8
                    for (int i2 = 0; i2 < WID; i2++)
                        fa += sm->Wt2[i2][k] * sm->h2[s >> 2][i2 * 4 + (s & 3)];
                    float f = g_g2[m][k] * fa + g_be2[m][k];
                    sm->fb[k][s] = f;
                    sm->ya[k][s] += wst * f;
                }
                if (tid < SPB) {
                    float dv = sm->wred[0][tid] + sm->wred[1][tid] +
                               sm->wred[2][tid] + sm->wred[3][tid];
                    sm->dlp[tid] += dt6 * wst * dv;
                }
            }
            __syncthreads();
        }
        // y += dt/6 * (f1 + 2 f2 + 2 f3 + f4)
        for (int idx = tid; idx < LDIM * SPB; idx += NTH) {
            int j = idx >> 4, s = idx & 15;
            sm->yb[j][s] += dt6 * sm->ya[j][s];
            sm->ya[j][s] = 0.0f;
        }
        __syncthreads();
    }

    // out = delta_logp + sum(-0.5 y^2 - 0.5 log(2pi))
    if (tid < SPB) {
        const int s = tid;
        float o = sm->dlp[s];
#pragma unroll
        for (int l = 0; l < LDIM; l++) {
            float yv = sm->yb[l][s];
            o += -0.5f * yv * yv - 0.5f * LOG2PI_F;
        }
        out[s0 + s] = o;
    }
}

// ---------------------------------------------------------------------------
extern "C" void kernel_launch(void* const* d_in, const int* in_sizes, int n_in,
                              void* d_out, int out_size)
{
    (void)in_sizes; (void)n_in; (void)out_size;
    const float* W1_0 = (const float*)d_in[0];
    const float* b1_0 = (const float*)d_in[1];
    const float* W2_0 = (const float*)d_in[2];
    const float* b2_0 = (const float*)d_in[3];
    const float* W3_0 = (const float*)d_in[4];
    const float* W1_1 = (const float*)d_in[5];
    const float* b1_1 = (const float*)d_in[6];
    const float* W2_1 = (const float*)d_in[7];
    const float* b2_1 = (const float*)d_in[8];
    const float* W3_1 = (const float*)d_in[9];
    const float* W1_2 = (const float*)d_in[10];
    const float* b1_2 = (const float*)d_in[11];
    const float* W2_2 = (const float*)d_in[12];
    const float* b2_2 = (const float*)d_in[13];
    const float* W3_2 = (const float*)d_in[14];
    const float* z    = (const float*)d_in[15];
    const float* cnd  = (const float*)d_in[16];
    float* out = (float*)d_out;

    cudaFuncSetAttribute(cnf_kernel, cudaFuncAttributeMaxDynamicSharedMemorySize,
                         (int)sizeof(SM));

    prep_kernel<<<NT, WID>>>(W1_0, b1_0, W2_0, b2_0, W3_0,
                             W1_1, b1_1, W2_1, b2_1, W3_1,
                             W1_2, b1_2, W2_2, b2_2, W3_2);

    cnf_kernel<<<BATCH / SPB, NTH, sizeof(SM)>>>(z, cnd, W1_0, W1_1, W1_2, out);
}

// round 2
// speedup vs baseline: 1.2444x; 1.2444x over previous
#include <cuda_runtime.h>

#define LDIM 16
#define CDIM 16
#define WID 128
#define BATCH 2048
#define NSTEPS 8
#define NT 17            // distinct t values: 1 - k/16, k=0..16
#define SPB 16           // samples per block
#define NTH 256
#define LOG2PI_F 1.8378770664093453f

typedef unsigned long long u64;

// Precomputed per-t tables (setup kernel fills these every launch)
__device__ float g_Qt[NT][WID][WID];        // Qt[m][j][i] = Q_m[i][j]
__device__ float g_g0[NT][WID], g_be0[NT][WID];
__device__ float g_g1[NT][WID], g_be1[NT][WID];
__device__ float g_g2[NT][LDIM], g_be2[NT][LDIM];

__device__ __forceinline__ float sigmoidf_(float x) {
    return __fdividef(1.0f, 1.0f + __expf(-x));
}
__device__ __forceinline__ float tanhf_(float x) {
    return 1.0f - __fdividef(2.0f, __expf(2.0f * x) + 1.0f);
}
__device__ __forceinline__ u64 pack2_(float lo, float hi) {
    u64 r; asm("mov.b64 %0, {%1, %2};" : "=l"(r) : "f"(lo), "f"(hi)); return r;
}
__device__ __forceinline__ void unpack2_(u64 v, float& lo, float& hi) {
    asm("mov.b64 {%0, %1}, %2;" : "=f"(lo), "=f"(hi) : "l"(v));
}
__device__ __forceinline__ void ffma2_(u64& d, u64 a, u64 b) {
    asm("fma.rn.f32x2 %0, %1, %2, %0;" : "+l"(d) : "l"(a), "l"(b));
}

// ---------------------------------------------------------------------------
// Setup: per t-value gates, effective biases, and divergence matrix Q(t).
// Q[i,j] = g1[i] * W1_1[i,j] * g0[j] * sum_k W1_0[j,k] * g2[k] * W1_2[k,i]
// ---------------------------------------------------------------------------
__global__ void prep_kernel(
    const float* __restrict__ W1_0, const float* __restrict__ b1_0,
    const float* __restrict__ W2_0, const float* __restrict__ b2_0,
    const float* __restrict__ W3_0,
    const float* __restrict__ W1_1, const float* __restrict__ b1_1,
    const float* __restrict__ W2_1, const float* __restrict__ b2_1,
    const float* __restrict__ W3_1,
    const float* __restrict__ W1_2, const float* __restrict__ b1_2,
    const float* __restrict__ W2_2, const float* __restrict__ b2_2,
    const float* __restrict__ W3_2)
{
    const int m = blockIdx.x;
    const int i = threadIdx.x;
    const float t = 1.0f - 0.0625f * (float)m;

    __shared__ float sg0[WID], sg1[WID], sg2[LDIM];

    {
        float g = sigmoidf_(W2_0[i] * t + b2_0[i]);
        sg0[i] = g;
        g_g0[m][i] = g;
        g_be0[m][i] = g * b1_0[i] + t * W3_0[i];

        float h = sigmoidf_(W2_1[i] * t + b2_1[i]);
        sg1[i] = h;
        g_g1[m][i] = h;
        g_be1[m][i] = h * b1_1[i] + t * W3_1[i];
    }
    if (i < LDIM) {
        float g = sigmoidf_(W2_2[i] * t + b2_2[i]);
        sg2[i] = g;
        g_g2[m][i] = g;
        g_be2[m][i] = g * b1_2[i] + t * W3_2[i];
    }
    __syncthreads();

    float a[LDIM];
#pragma unroll
    for (int k = 0; k < LDIM; k++) a[k] = sg2[k] * W1_2[k * WID + i];
    const float g1i = sg1[i];

    for (int j = 0; j < WID; j++) {
        float p = 0.0f;
#pragma unroll
        for (int k = 0; k < LDIM; k++) p += W1_0[j * (LDIM + CDIM) + k] * a[k];
        g_Qt[m][j][i] = g1i * W1_1[i * WID + j] * (sg0[j] * p);
    }
}

// ---------------------------------------------------------------------------
// Main persistent kernel: each block integrates 16 samples through all
// 8 RK4 steps. 256 threads: neuron i = tid&127, sample-half hs = tid>>7.
// Activation layout [q][neuron*4 + c], sample s = 4q + c -> packed-pair
// friendly (ulonglong2 = two f32x2 operands) and bank-conflict-free.
// ---------------------------------------------------------------------------
struct SM {
    float Wt0[LDIM + CDIM][WID];   // Wt0[j][i] = W1_0[i][j]
    float Wt1[WID][WID];           // Wt1[j][i] = W1_1[i][j]
    float Wt2[WID][LDIM];          // Wt2[i][k] = W1_2[k][i]
    float x [4][(LDIM + CDIM) * 4];
    float h1[4][WID * 4];
    float d1[4][WID * 4];
    float h2[4][WID * 4];
    float fb[LDIM][SPB];
    float yb[LDIM][SPB];
    float ya[LDIM][SPB];
    float dlp[SPB];
    float wred[8][8];
};

__global__ void __launch_bounds__(NTH, 1)
cnf_kernel(const float* __restrict__ z, const float* __restrict__ cond,
           const float* __restrict__ W1_0, const float* __restrict__ W1_1,
           const float* __restrict__ W1_2, float* __restrict__ out)
{
    extern __shared__ float smraw[];
    SM* sm = reinterpret_cast<SM*>(smraw);
    const int tid  = threadIdx.x;
    const int lane = tid & 31;
    const int wrp  = tid >> 5;
    const int i    = tid & 127;       // neuron
    const int hs   = tid >> 7;        // sample half: q groups {2hs, 2hs+1}
    const int s0   = blockIdx.x * SPB;

    // --- load transposed weights into smem (one-time cost) ---
    for (int idx = tid; idx < WID * (LDIM + CDIM); idx += NTH) {
        int r = idx >> 5, j = idx & 31;
        sm->Wt0[j][r] = W1_0[idx];
    }
    for (int idx = tid; idx < WID * WID; idx += NTH) {
        int r = idx >> 7, j = idx & 127;
        sm->Wt1[j][r] = W1_1[idx];
    }
    for (int idx = tid; idx < LDIM * WID; idx += NTH) {
        int k = idx >> 7, r = idx & 127;
        sm->Wt2[r][k] = W1_2[idx];
    }
    // --- per-sample state ---
    {
        int idx = tid;                       // SPB*LDIM = 256 = NTH
        int s = idx >> 4, l = idx & 15;
        sm->yb[l][s] = z[(s0 + s) * LDIM + l];
        sm->ya[l][s] = 0.0f;
        int s2 = idx >> 4, c = idx & 15;     // SPB*CDIM = 256
        sm->x[s2 >> 2][(LDIM + c) * 4 + (s2 & 3)] = cond[(s0 + s2) * CDIM + c];
    }
    if (tid < SPB) sm->dlp[tid] = 0.0f;
    __syncthreads();

    const float dt  = -0.125f;
    const float dt6 = dt * (1.0f / 6.0f);

    for (int step = 0; step < NSTEPS; step++) {
        for (int st = 0; st < 4; st++) {
            const int   m    = 2 * step + ((st == 0) ? 0 : ((st == 3) ? 2 : 1));
            const float coef = (st == 0) ? 0.0f : ((st == 3) ? dt : 0.5f * dt);
            const float wst  = (st == 1 || st == 2) ? 2.0f : 1.0f;

            // stage input y-part: y + coef * f_prev  (LDIM*SPB = 256 = NTH)
            {
                int j = tid >> 4, s = tid & 15;
                float v = sm->yb[j][s];
                if (st) v += coef * sm->fb[j][s];
                sm->x[s >> 2][j * 4 + (s & 3)] = v;
            }
            __syncthreads();

            // ----- layer 0: 32 -> 128 (8 samples/thread, packed pairs) -----
            u64 acc[4];
#pragma unroll
            for (int p = 0; p < 4; p++) acc[p] = 0ull;
#pragma unroll 4
            for (int j = 0; j < LDIM + CDIM; j++) {
                float w = sm->Wt0[j][i];
                u64 w2 = pack2_(w, w);
#pragma unroll
                for (int qq = 0; qq < 2; qq++) {
                    const ulonglong2 xv =
                        *reinterpret_cast<const ulonglong2*>(&sm->x[hs * 2 + qq][j * 4]);
                    ffma2_(acc[qq * 2 + 0], w2, xv.x);
                    ffma2_(acc[qq * 2 + 1], w2, xv.y);
                }
            }
            {
                const float g = g_g0[m][i], be = g_be0[m][i];
#pragma unroll
                for (int qq = 0; qq < 2; qq++) {
                    float4 hv, dv;
                    float a0, a1, a2, a3, h;
                    unpack2_(acc[qq * 2 + 0], a0, a1);
                    unpack2_(acc[qq * 2 + 1], a2, a3);
                    h = tanhf_(g * a0 + be); hv.x = h; dv.x = 1.0f - h * h;
                    h = tanhf_(g * a1 + be); hv.y = h; dv.y = 1.0f - h * h;
                    h = tanhf_(g * a2 + be); hv.z = h; dv.z = 1.0f - h * h;
                    h = tanhf_(g * a3 + be); hv.w = h; dv.w = 1.0f - h * h;
                    *reinterpret_cast<float4*>(&sm->h1[hs * 2 + qq][i * 4]) = hv;
                    *reinterpret_cast<float4*>(&sm->d1[hs * 2 + qq][i * 4]) = dv;
                }
            }
            __syncthreads();

            // ----- fused layer 1 (128x128) + divergence matvec u = Q d1 -----
            u64 acc2[4];
#pragma unroll
            for (int p = 0; p < 4; p++) { acc[p] = 0ull; acc2[p] = 0ull; }
            const float* qcol = &g_Qt[m][0][i];
#pragma unroll 4
            for (int j = 0; j < WID; j++) {
                float w  = sm->Wt1[j][i];
                float qv = __ldg(qcol + j * WID);
                u64 w2 = pack2_(w, w);
                u64 q2 = pack2_(qv, qv);
#pragma unroll
                for (int qq = 0; qq < 2; qq++) {
                    const ulonglong2 hv =
                        *reinterpret_cast<const ulonglong2*>(&sm->h1[hs * 2 + qq][j * 4]);
                    const ulonglong2 dv =
                        *reinterpret_cast<const ulonglong2*>(&sm->d1[hs * 2 + qq][j * 4]);
                    ffma2_(acc [qq * 2 + 0], w2, hv.x);
                    ffma2_(acc [qq * 2 + 1], w2, hv.y);
                    ffma2_(acc2[qq * 2 + 0], q2, dv.x);
                    ffma2_(acc2[qq * 2 + 1], q2, dv.y);
                }
            }
            {
                const float g = g_g1[m][i], be = g_be1[m][i];
                float v[8];
#pragma unroll
                for (int qq = 0; qq < 2; qq++) {
                    float4 hv;
                    float a0, a1, a2, a3, u0, u1, u2, u3, h;
                    unpack2_(acc [qq * 2 + 0], a0, a1);
                    unpack2_(acc [qq * 2 + 1], a2, a3);
                    unpack2_(acc2[qq * 2 + 0], u0, u1);
                    unpack2_(acc2[qq * 2 + 1], u2, u3);
                    h = tanhf_(g * a0 + be); hv.x = h; v[qq * 4 + 0] = u0 * (1.0f - h * h);
                    h = tanhf_(g * a1 + be); hv.y = h; v[qq * 4 + 1] = u1 * (1.0f - h * h);
                    h = tanhf_(g * a2 + be); hv.z = h; v[qq * 4 + 2] = u2 * (1.0f - h * h);
                    h = tanhf_(g * a3 + be); hv.w = h; v[qq * 4 + 3] = u3 * (1.0f - h * h);
                    *reinterpret_cast<float4*>(&sm->h2[hs * 2 + qq][i * 4]) = hv;
                }
                // divergence: reduce over neurons (32 per warp), per local sample ls
#pragma unroll
                for (int ls = 0; ls < 8; ls++) {
                    float r = v[ls];
                    r += __shfl_xor_sync(0xffffffffu, r, 16);
                    r += __shfl_xor_sync(0xffffffffu, r, 8);
                    r += __shfl_xor_sync(0xffffffffu, r, 4);
                    r += __shfl_xor_sync(0xffffffffu, r, 2);
                    r += __shfl_xor_sync(0xffffffffu, r, 1);
                    if (lane == 0) sm->wred[wrp][ls] = r;
                }
            }
            __syncthreads();

            // ----- layer 2: 128 -> 16, one (k,s) per thread -----
            {
                const int k = tid & 15;
                const int s = tid >> 4;
                float fa = 0.0f;
#pragma unroll 8
                for (int i2 = 0; i2 < WID; i2++)
                    fa += sm->Wt2[i2][k] * sm->h2[s >> 2][i2 * 4 + (s & 3)];
                float f = g_g2[m][k] * fa + g_be2[m][k];
                sm->fb[k][s] = f;
                sm->ya[k][s] += wst * f;

                if (tid < SPB) {
                    const int sh = tid >> 3;   // which half this sample lives in
                    const int ls = tid & 7;
                    float dv = sm->wred[sh * 4 + 0][ls] + sm->wred[sh * 4 + 1][ls] +
                               sm->wred[sh * 4 + 2][ls] + sm->wred[sh * 4 + 3][ls];
                    sm->dlp[tid] += dt6 * wst * dv;
                }
            }
            __syncthreads();
        }
        // y += dt/6 * (f1 + 2 f2 + 2 f3 + f4)   (256 elems = NTH)
        {
            int j = tid >> 4, s = tid & 15;
            sm->yb[j][s] += dt6 * sm->ya[j][s];
            sm->ya[j][s] = 0.0f;
        }
        __syncthreads();
    }

    // out = delta_logp + sum(-0.5 y^2 - 0.5 log(2pi))
    if (tid < SPB) {
        const int s = tid;
        float o = sm->dlp[s];
#pragma unroll
        for (int l = 0; l < LDIM; l++) {
            float yv = sm->yb[l][s];
            o += -0.5f * yv * yv - 0.5f * LOG2PI_F;
        }
        out[s0 + s] = o;
    }
}

// ---------------------------------------------------------------------------
extern "C" void kernel_launch(void* const* d_in, const int* in_sizes, int n_in,
                              void* d_out, int out_size)
{
    (void)in_sizes; (void)n_in; (void)out_size;
    const float* W1_0 = (const float*)d_in[0];
    const float* b1_0 = (const float*)d_in[1];
    const float* W2_0 = (const float*)d_in[2];
    const float* b2_0 = (const float*)d_in[3];
    const float* W3_0 = (const float*)d_in[4];
    const float* W1_1 = (const float*)d_in[5];
    const float* b1_1 = (const float*)d_in[6];
    const float* W2_1 = (const float*)d_in[7];
    const float* b2_1 = (const float*)d_in[8];
    const float* W3_1 = (const float*)d_in[9];
    const float* W1_2 = (const float*)d_in[10];
    const float* b1_2 = (const float*)d_in[11];
    const float* W2_2 = (const float*)d_in[12];
    const float* b2_2 = (const float*)d_in[13];
    const float* W3_2 = (const float*)d_in[14];
    const float* z    = (const float*)d_in[15];
    const float* cnd  = (const float*)d_in[16];
    float* out = (float*)d_out;

    cudaFuncSetAttribute(cnf_kernel, cudaFuncAttributeMaxDynamicSharedMemorySize,
                         (int)sizeof(SM));

    prep_kernel<<<NT, WID>>>(W1_0, b1_0, W2_0, b2_0, W3_0,
                             W1_1, b1_1, W2_1, b2_1, W3_1,
                             W1_2, b1_2, W2_2, b2_2, W3_2);

    cnf_kernel<<<BATCH / SPB, NTH, sizeof(SM)>>>(z, cnd, W1_0, W1_1, W1_2, out);
}

// round 3
// speedup vs baseline: 1.2457x; 1.0010x over previous
#include <cuda_runtime.h>

#define LDIM 16
#define CDIM 16
#define WID 128
#define BATCH 2048
#define NSTEPS 8
#define NT 17            // distinct t values: 1 - k/16, k=0..16
#define SPB 16           // samples per block
#define NTH 512
#define LOG2PI_F 1.8378770664093453f

typedef unsigned long long u64;

// Precomputed per-t tables (prep kernel fills these every launch)
__device__ float2 g_WQ[NT][WID][WID];   // [m][j][i] = (W1_1[i][j], Q_m[i][j])
__device__ float  g_Qs[NT][WID];        // Qsum[m][i] = sum_j Q_m[i][j]
__device__ float g_g0[NT][WID], g_be0[NT][WID];
__device__ float g_g1[NT][WID], g_be1[NT][WID];
__device__ float g_g2[NT][LDIM], g_be2[NT][LDIM];

__device__ __forceinline__ float sigmoidf_(float x) {
    return __fdividef(1.0f, 1.0f + __expf(-x));
}
__device__ __forceinline__ float tanhf_(float x) {
    return 1.0f - __fdividef(2.0f, __expf(2.0f * x) + 1.0f);
}
__device__ __forceinline__ u64 pack2_(float lo, float hi) {
    u64 r; asm("mov.b64 %0, {%1, %2};" : "=l"(r) : "f"(lo), "f"(hi)); return r;
}
__device__ __forceinline__ void unpack2_(u64 v, float& lo, float& hi) {
    asm("mov.b64 {%0, %1}, %2;" : "=f"(lo), "=f"(hi) : "l"(v));
}
__device__ __forceinline__ void ffma2_(u64& d, u64 a, u64 b) {
    asm("fma.rn.f32x2 %0, %1, %2, %0;" : "+l"(d) : "l"(a), "l"(b));
}

// ---------------------------------------------------------------------------
// Setup: per t-value gates, effective biases, fused (W1_1, Q) table, Qsum.
// Q[i,j] = g1[i] * W1_1[i,j] * g0[j] * sum_k W1_0[j,k] * g2[k] * W1_2[k,i]
// ---------------------------------------------------------------------------
__global__ void prep_kernel(
    const float* __restrict__ W1_0, const float* __restrict__ b1_0,
    const float* __restrict__ W2_0, const float* __restrict__ b2_0,
    const float* __restrict__ W3_0,
    const float* __restrict__ W1_1, const float* __restrict__ b1_1,
    const float* __restrict__ W2_1, const float* __restrict__ b2_1,
    const float* __restrict__ W3_1,
    const float* __restrict__ W1_2, const float* __restrict__ b1_2,
    const float* __restrict__ W2_2, const float* __restrict__ b2_2,
    const float* __restrict__ W3_2)
{
    const int m = blockIdx.x;
    const int i = threadIdx.x;
    const float t = 1.0f - 0.0625f * (float)m;

    __shared__ float sg0[WID], sg1[WID], sg2[LDIM];

    {
        float g = sigmoidf_(W2_0[i] * t + b2_0[i]);
        sg0[i] = g;
        g_g0[m][i] = g;
        g_be0[m][i] = g * b1_0[i] + t * W3_0[i];

        float h = sigmoidf_(W2_1[i] * t + b2_1[i]);
        sg1[i] = h;
        g_g1[m][i] = h;
        g_be1[m][i] = h * b1_1[i] + t * W3_1[i];
    }
    if (i < LDIM) {
        float g = sigmoidf_(W2_2[i] * t + b2_2[i]);
        sg2[i] = g;
        g_g2[m][i] = g;
        g_be2[m][i] = g * b1_2[i] + t * W3_2[i];
    }
    __syncthreads();

    float a[LDIM];
#pragma unroll
    for (int k = 0; k < LDIM; k++) a[k] = sg2[k] * W1_2[k * WID + i];
    const float g1i = sg1[i];

    float qsum = 0.0f;
    for (int j = 0; j < WID; j++) {
        float p = 0.0f;
#pragma unroll
        for (int k = 0; k < LDIM; k++) p += W1_0[j * (LDIM + CDIM) + k] * a[k];
        float w1 = W1_1[i * WID + j];
        float q  = g1i * w1 * (sg0[j] * p);
        qsum += q;
        g_WQ[m][j][i] = make_float2(w1, q);
    }
    g_Qs[m][i] = qsum;
}

// ---------------------------------------------------------------------------
// Main kernel: 512 threads, 16 samples per block, all 8 RK4 steps in-block.
// Thread = (neuron i = tid&127, sample-quarter hs = tid>>7).
// Activation layout [q][neuron*4 + c], sample s = 4q + c.
// ---------------------------------------------------------------------------
struct SM {
    float Wt0[LDIM + CDIM][WID];   // Wt0[j][i] = W1_0[i][j]
    float Wt2[WID][LDIM];          // Wt2[i][k] = W1_2[k][i]
    float x  [4][(LDIM + CDIM) * 4];
    float h1 [4][WID * 4];
    float hsq[4][WID * 4];         // h1^2
    float h2 [4][WID * 4];
    float yb[LDIM][SPB + 1];       // padded stride 17 (bank conflicts)
    float ya[LDIM][SPB + 1];
    float dlp[SPB];
    float wred[16][4];
};

__global__ void __launch_bounds__(NTH, 1)
cnf_kernel(const float* __restrict__ z, const float* __restrict__ cond,
           const float* __restrict__ W1_0, const float* __restrict__ W1_2,
           float* __restrict__ out)
{
    extern __shared__ float smraw[];
    SM* sm = reinterpret_cast<SM*>(smraw);
    const int tid  = threadIdx.x;
    const int lane = tid & 31;
    const int wrp  = tid >> 5;
    const int i    = tid & 127;       // neuron
    const int hs   = tid >> 7;        // sample quarter (q group)
    const int s0   = blockIdx.x * SPB;

    // --- transposed weights into smem ---
    for (int idx = tid; idx < WID * (LDIM + CDIM); idx += NTH) {
        int r = idx >> 5, j = idx & 31;
        sm->Wt0[j][r] = W1_0[idx];
    }
    for (int idx = tid; idx < LDIM * WID; idx += NTH) {
        int k = idx >> 7, r = idx & 127;
        sm->Wt2[r][k] = W1_2[idx];
    }
    // --- per-sample state + initial stage input x (t=1: x = z) ---
    if (tid < SPB * LDIM) {
        int s = tid >> 4, l = tid & 15;
        float zv = z[(s0 + s) * LDIM + l];
        sm->yb[l][s] = zv;
        sm->ya[l][s] = 0.0f;
        sm->x[s >> 2][l * 4 + (s & 3)] = zv;
        float cv = cond[(s0 + s) * CDIM + l];
        sm->x[s >> 2][(LDIM + l) * 4 + (s & 3)] = cv;
    }
    if (tid < SPB) sm->dlp[tid] = 0.0f;
    __syncthreads();

    const float dt  = -0.125f;
    const float dt6 = dt * (1.0f / 6.0f);

    for (int e = 0; e < 4 * NSTEPS; e++) {
        const int step = e >> 2, st = e & 3;
        const int   m   = 2 * step + ((st == 0) ? 0 : ((st == 3) ? 2 : 1));
        const float wst = (st == 1 || st == 2) ? 2.0f : 1.0f;

        // ----- layer 0: 32 -> 128, 4 samples/thread -----
        {
            u64 a0 = 0ull, a1 = 0ull;
#pragma unroll 8
            for (int j = 0; j < LDIM + CDIM; j++) {
                float w = sm->Wt0[j][i];
                u64 w2 = pack2_(w, w);
                const ulonglong2 xv =
                    *reinterpret_cast<const ulonglong2*>(&sm->x[hs][j * 4]);
                ffma2_(a0, w2, xv.x);
                ffma2_(a1, w2, xv.y);
            }
            const float g = g_g0[m][i], be = g_be0[m][i];
            float v0, v1, v2, v3, h;
            unpack2_(a0, v0, v1);
            unpack2_(a1, v2, v3);
            float4 hv, sv;
            h = tanhf_(g * v0 + be); hv.x = h; sv.x = h * h;
            h = tanhf_(g * v1 + be); hv.y = h; sv.y = h * h;
            h = tanhf_(g * v2 + be); hv.z = h; sv.z = h * h;
            h = tanhf_(g * v3 + be); hv.w = h; sv.w = h * h;
            *reinterpret_cast<float4*>(&sm->h1 [hs][i * 4]) = hv;
            *reinterpret_cast<float4*>(&sm->hsq[hs][i * 4]) = sv;
        }
        __syncthreads();

        // ----- fused layer 1 (W acc) + divergence (Q acc on h^2) -----
        {
            u64 a0 = 0ull, a1 = 0ull, b0 = 0ull, b1 = 0ull;
            const float2* wqp = &g_WQ[m][0][i];
#pragma unroll 8
            for (int j = 0; j < WID; j++) {
                float2 wq = __ldg(wqp + j * WID);
                u64 w2 = pack2_(wq.x, wq.x);
                u64 q2 = pack2_(wq.y, wq.y);
                const ulonglong2 hv =
                    *reinterpret_cast<const ulonglong2*>(&sm->h1 [hs][j * 4]);
                const ulonglong2 sv =
                    *reinterpret_cast<const ulonglong2*>(&sm->hsq[hs][j * 4]);
                ffma2_(a0, w2, hv.x);
                ffma2_(a1, w2, hv.y);
                ffma2_(b0, q2, sv.x);
                ffma2_(b1, q2, sv.y);
            }
            const float g = g_g1[m][i], be = g_be1[m][i];
            const float qs = g_Qs[m][i];
            float v0, v1, v2, v3, u0, u1, u2, u3, h;
            unpack2_(a0, v0, v1);
            unpack2_(a1, v2, v3);
            unpack2_(b0, u0, u1);
            unpack2_(b1, u2, u3);
            float4 hv;
            float vdiv[4];
            h = tanhf_(g * v0 + be); hv.x = h; vdiv[0] = (qs - u0) * (1.0f - h * h);
            h = tanhf_(g * v1 + be); hv.y = h; vdiv[1] = (qs - u1) * (1.0f - h * h);
            h = tanhf_(g * v2 + be); hv.z = h; vdiv[2] = (qs - u2) * (1.0f - h * h);
            h = tanhf_(g * v3 + be); hv.w = h; vdiv[3] = (qs - u3) * (1.0f - h * h);
            *reinterpret_cast<float4*>(&sm->h2[hs][i * 4]) = hv;
            // reduce each of 4 local samples over the warp's 32 neurons
#pragma unroll
            for (int c = 0; c < 4; c++) {
                float r = vdiv[c];
                r += __shfl_xor_sync(0xffffffffu, r, 16);
                r += __shfl_xor_sync(0xffffffffu, r, 8);
                r += __shfl_xor_sync(0xffffffffu, r, 4);
                r += __shfl_xor_sync(0xffffffffu, r, 2);
                r += __shfl_xor_sync(0xffffffffu, r, 1);
                if (lane == 0) sm->wred[wrp][c] = r;
            }
        }
        __syncthreads();

        // ----- layer 2 (128->16) + state update + next-stage input -----
        {
            const int p = tid >> 1;          // (k,s) pair, 256 of them
            const int half = tid & 1;        // even/odd i2 split
            const int k = p & 15;
            const int s = p >> 4;
            const float* h2row = &sm->h2[s >> 2][s & 3];
            float fa = 0.0f;
#pragma unroll 8
            for (int n = 0; n < WID / 2; n++) {
                int i2 = 2 * n + half;
                fa += sm->Wt2[i2][k] * h2row[i2 * 4];
            }
            fa += __shfl_xor_sync(0xffffffffu, fa, 1);
            if (half == 0) {
                float f = g_g2[m][k] * fa + g_be2[m][k];
                float yav = sm->ya[k][s] + wst * f;
                if (st < 3) {
                    sm->ya[k][s] = yav;
                    float cn = (st == 2) ? dt : 0.5f * dt;
                    sm->x[s >> 2][k * 4 + (s & 3)] = sm->yb[k][s] + cn * f;
                } else {
                    float ybv = sm->yb[k][s] + dt6 * yav;
                    sm->yb[k][s] = ybv;
                    sm->ya[k][s] = 0.0f;
                    sm->x[s >> 2][k * 4 + (s & 3)] = ybv;
                }
            }
            if (tid < SPB) {
                const int sb = (tid >> 2) * 4, c = tid & 3;
                float dv = sm->wred[sb + 0][c] + sm->wred[sb + 1][c] +
                           sm->wred[sb + 2][c] + sm->wred[sb + 3][c];
                sm->dlp[tid] += dt6 * wst * dv;
            }
        }
        __syncthreads();
    }

    // out = delta_logp + sum(-0.5 y^2 - 0.5 log(2pi))
    if (tid < SPB) {
        const int s = tid;
        float o = sm->dlp[s];
#pragma unroll
        for (int l = 0; l < LDIM; l++) {
            float yv = sm->yb[l][s];
            o += -0.5f * yv * yv - 0.5f * LOG2PI_F;
        }
        out[s0 + s] = o;
    }
}

// ---------------------------------------------------------------------------
extern "C" void kernel_launch(void* const* d_in, const int* in_sizes, int n_in,
                              void* d_out, int out_size)
{
    (void)in_sizes; (void)n_in; (void)out_size;
    const float* W1_0 = (const float*)d_in[0];
    const float* b1_0 = (const float*)d_in[1];
    const float* W2_0 = (const float*)d_in[2];
    const float* b2_0 = (const float*)d_in[3];
    const float* W3_0 = (const float*)d_in[4];
    const float* W1_1 = (const float*)d_in[5];
    const float* b1_1 = (const float*)d_in[6];
    const float* W2_1 = (const float*)d_in[7];
    const float* b2_1 = (const float*)d_in[8];
    const float* W3_1 = (const float*)d_in[9];
    const float* W1_2 = (const float*)d_in[10];
    const float* b1_2 = (const float*)d_in[11];
    const float* W2_2 = (const float*)d_in[12];
    const float* b2_2 = (const float*)d_in[13];
    const float* W3_2 = (const float*)d_in[14];
    const float* z    = (const float*)d_in[15];
    const float* cnd  = (const float*)d_in[16];
    float* out = (float*)d_out;

    cudaFuncSetAttribute(cnf_kernel, cudaFuncAttributeMaxDynamicSharedMemorySize,
                         (int)sizeof(SM));

    prep_kernel<<<NT, WID>>>(W1_0, b1_0, W2_0, b2_0, W3_0,
                             W1_1, b1_1, W2_1, b2_1, W3_1,
                             W1_2, b1_2, W2_2, b2_2, W3_2);

    cnf_kernel<<<BATCH / SPB, NTH, sizeof(SM)>>>(z, cnd, W1_0, W1_2, out);
}

// round 5
// speedup vs baseline: 1.2881x; 1.0340x over previous
#include <cuda_runtime.h>

#define LDIM 16
#define CDIM 16
#define WID 128
#define BATCH 2048
#define NSTEPS 8
#define NT 17            // distinct t values: 1 - k/16, k=0..16
#define SPB 16           // samples per block
#define NTH 512
#define LOG2PI_F 1.8378770664093453f

typedef unsigned long long u64;

// Precomputed per-t tables (prep kernel fills these every launch)
// g_WE[m][j][i] = ( W1_1[i][j],  E_m[j][i] = W1_1[i][j] * P_m[j][i] )
// P_m[j][i] = sum_k W1_0[j][k] * g2_m[k] * W1_2[k][i]
__device__ float2 g_WE[NT][WID][WID];
__device__ float g_g0[NT][WID], g_be0[NT][WID];
__device__ float g_g1[NT][WID], g_be1[NT][WID];
__device__ float g_g2[NT][LDIM], g_be2[NT][LDIM];

__device__ __forceinline__ float sigmoidf_(float x) {
    return __fdividef(1.0f, 1.0f + __expf(-x));
}
__device__ __forceinline__ float tanhf_(float x) {
    return 1.0f - __fdividef(2.0f, __expf(2.0f * x) + 1.0f);
}
__device__ __forceinline__ u64 pack2_(float lo, float hi) {
    u64 r; asm("mov.b64 %0, {%1, %2};" : "=l"(r) : "f"(lo), "f"(hi)); return r;
}
__device__ __forceinline__ void unpack2_(u64 v, float& lo, float& hi) {
    asm("mov.b64 {%0, %1}, %2;" : "=f"(lo), "=f"(hi) : "l"(v));
}
__device__ __forceinline__ void ffma2_(u64& d, u64 a, u64 b) {
    asm("fma.rn.f32x2 %0, %1, %2, %0;" : "+l"(d) : "l"(a), "l"(b));
}

// ---------------------------------------------------------------------------
// Setup kernel
// ---------------------------------------------------------------------------
__global__ void prep_kernel(
    const float* __restrict__ W1_0, const float* __restrict__ b1_0,
    const float* __restrict__ W2_0, const float* __restrict__ b2_0,
    const float* __restrict__ W3_0,
    const float* __restrict__ W1_1, const float* __restrict__ b1_1,
    const float* __restrict__ W2_1, const float* __restrict__ b2_1,
    const float* __restrict__ W3_1,
    const float* __restrict__ W1_2, const float* __restrict__ b1_2,
    const float* __restrict__ W2_2, const float* __restrict__ b2_2,
    const float* __restrict__ W3_2)
{
    const int m = blockIdx.x;
    const int i = threadIdx.x;
    const float t = 1.0f - 0.0625f * (float)m;

    __shared__ float sg2[LDIM];

    {
        float g = sigmoidf_(W2_0[i] * t + b2_0[i]);
        g_g0[m][i] = g;
        g_be0[m][i] = g * b1_0[i] + t * W3_0[i];

        float h = sigmoidf_(W2_1[i] * t + b2_1[i]);
        g_g1[m][i] = h;
        g_be1[m][i] = h * b1_1[i] + t * W3_1[i];
    }
    if (i < LDIM) {
        float g = sigmoidf_(W2_2[i] * t + b2_2[i]);
        sg2[i] = g;
        g_g2[m][i] = g;
        g_be2[m][i] = g * b1_2[i] + t * W3_2[i];
    }
    __syncthreads();

    float a[LDIM];
#pragma unroll
    for (int k = 0; k < LDIM; k++) a[k] = sg2[k] * W1_2[k * WID + i];

    for (int j = 0; j < WID; j++) {
        float p = 0.0f;
#pragma unroll
        for (int k = 0; k < LDIM; k++) p += W1_0[j * (LDIM + CDIM) + k] * a[k];
        float w1 = W1_1[i * WID + j];
        g_WE[m][j][i] = make_float2(w1, w1 * p);
    }
}

// ---------------------------------------------------------------------------
// Main kernel: 512 threads, 16 samples/block, all 8 RK4 steps in-block.
// Thread = (neuron i = tid&127, sample-quarter hs = tid>>7), 4 samples each.
// Activation layout [q][neuron*4 + c], sample s = 4q + c.
// ---------------------------------------------------------------------------
struct SM {
    float Wt0y[LDIM][WID];         // Wt0y[j][i] = W1_0[i][j], y-part only
    float Wt2[WID][LDIM];          // Wt2[i][k] = W1_2[k][i]
    float x  [4][LDIM * 4];        // stage input (y part only)
    float h1 [4][WID * 4];
    float zz [4][WID * 4];         // g0 * (1 - h1^2)
    float h2 [4][WID * 4];
    float yb[LDIM][SPB + 1];
    float ya[LDIM][SPB + 1];
    float dlp[SPB];
    float wred[16][4];
};

__global__ void __launch_bounds__(NTH, 1)
cnf_kernel(const float* __restrict__ z, const float* __restrict__ cond,
           const float* __restrict__ W1_0, const float* __restrict__ W1_2,
           float* __restrict__ out)
{
    extern __shared__ float smraw[];
    SM* sm = reinterpret_cast<SM*>(smraw);
    const int tid  = threadIdx.x;
    const int lane = tid & 31;
    const int wrp  = tid >> 5;
    const int i    = tid & 127;       // neuron
    const int hs   = tid >> 7;        // sample quarter (q group)
    const int s0   = blockIdx.x * SPB;

    // --- weights into smem ---
    for (int idx = tid; idx < WID * LDIM; idx += NTH) {
        int r = idx >> 4, j = idx & 15;
        sm->Wt0y[j][r] = W1_0[r * (LDIM + CDIM) + j];
    }
    for (int idx = tid; idx < LDIM * WID; idx += NTH) {
        int k = idx >> 7, r = idx & 127;
        sm->Wt2[r][k] = W1_2[idx];
    }
    // --- per-sample state + initial stage input (t=1: x = z) ---
    if (tid < SPB * LDIM) {
        int s = tid >> 4, l = tid & 15;
        float zv = z[(s0 + s) * LDIM + l];
        sm->yb[l][s] = zv;
        sm->ya[l][s] = 0.0f;
        sm->x[s >> 2][l * 4 + (s & 3)] = zv;
    }
    if (tid < SPB) sm->dlp[tid] = 0.0f;

    // --- stage-invariant condition term for layer 0, kept in registers ---
    float cacc0 = 0.0f, cacc1 = 0.0f, cacc2 = 0.0f, cacc3 = 0.0f;
#pragma unroll 4
    for (int c = 0; c < CDIM; c++) {
        float w = __ldg(&W1_0[i * (LDIM + CDIM) + LDIM + c]);
        cacc0 += w * __ldg(&cond[(s0 + hs * 4 + 0) * CDIM + c]);
        cacc1 += w * __ldg(&cond[(s0 + hs * 4 + 1) * CDIM + c]);
        cacc2 += w * __ldg(&cond[(s0 + hs * 4 + 2) * CDIM + c]);
        cacc3 += w * __ldg(&cond[(s0 + hs * 4 + 3) * CDIM + c]);
    }
    const u64 ct0 = pack2_(cacc0, cacc1);
    const u64 ct1 = pack2_(cacc2, cacc3);
    __syncthreads();

    const float dt  = -0.125f;
    const float dt6 = dt * (1.0f / 6.0f);

    for (int e = 0; e < 4 * NSTEPS; e++) {
        const int step = e >> 2, st = e & 3;
        const int   m   = 2 * step + ((st == 0) ? 0 : ((st == 3) ? 2 : 1));
        const float wst = (st == 1 || st == 2) ? 2.0f : 1.0f;

        // ----- layer 0: 16 y-cols (+ cached cond term), 4 samples/thread ---
        {
            u64 a0 = ct0, a1 = ct1;
#pragma unroll
            for (int j = 0; j < LDIM; j++) {
                float w = sm->Wt0y[j][i];
                u64 w2 = pack2_(w, w);
                const ulonglong2 xv =
                    *reinterpret_cast<const ulonglong2*>(&sm->x[hs][j * 4]);
                ffma2_(a0, w2, xv.x);
                ffma2_(a1, w2, xv.y);
            }
            const float g = g_g0[m][i], be = g_be0[m][i];
            float v0, v1, v2, v3, h;
            unpack2_(a0, v0, v1);
            unpack2_(a1, v2, v3);
            float4 hv, zv;
            h = tanhf_(g * v0 + be); hv.x = h; zv.x = g * (1.0f - h * h);
            h = tanhf_(g * v1 + be); hv.y = h; zv.y = g * (1.0f - h * h);
            h = tanhf_(g * v2 + be); hv.z = h; zv.z = g * (1.0f - h * h);
            h = tanhf_(g * v3 + be); hv.w = h; zv.w = g * (1.0f - h * h);
            *reinterpret_cast<float4*>(&sm->h1[hs][i * 4]) = hv;
            *reinterpret_cast<float4*>(&sm->zz[hs][i * 4]) = zv;
        }
        __syncthreads();

        // ----- fused layer 1 (W acc) + divergence (E acc on z) -------------
        // software-pipelined LDG prefetch, depth 8, ping-pong buffers
        {
            u64 a0 = 0ull, a1 = 0ull, b0 = 0ull, b1 = 0ull;
            const float2* wep = &g_WE[m][0][i];
            float2 bufA[8], bufB[8];
#pragma unroll
            for (int jj = 0; jj < 8; jj++) bufA[jj] = __ldg(wep + jj * WID);
#pragma unroll 1
            for (int g4 = 0; g4 < 8; g4++) {
                const int j0 = g4 * 16;
#pragma unroll
                for (int jj = 0; jj < 8; jj++)
                    bufB[jj] = __ldg(wep + (j0 + 8 + jj) * WID);
#pragma unroll
                for (int jj = 0; jj < 8; jj++) {
                    const int j = j0 + jj;
                    u64 w2 = pack2_(bufA[jj].x, bufA[jj].x);
                    u64 q2 = pack2_(bufA[jj].y, bufA[jj].y);
                    const ulonglong2 hv =
                        *reinterpret_cast<const ulonglong2*>(&sm->h1[hs][j * 4]);
                    const ulonglong2 zv =
                        *reinterpret_cast<const ulonglong2*>(&sm->zz[hs][j * 4]);
                    ffma2_(a0, w2, hv.x);
                    ffma2_(a1, w2, hv.y);
                    ffma2_(b0, q2, zv.x);
                    ffma2_(b1, q2, zv.y);
                }
                if (g4 < 7) {
#pragma unroll
                    for (int jj = 0; jj < 8; jj++)
                        bufA[jj] = __ldg(wep + (j0 + 16 + jj) * WID);
                }
#pragma unroll
                for (int jj = 0; jj < 8; jj++) {
                    const int j = j0 + 8 + jj;
                    u64 w2 = pack2_(bufB[jj].x, bufB[jj].x);
                    u64 q2 = pack2_(bufB[jj].y, bufB[jj].y);
                    const ulonglong2 hv =
                        *reinterpret_cast<const ulonglong2*>(&sm->h1[hs][j * 4]);
                    const ulonglong2 zv =
                        *reinterpret_cast<const ulonglong2*>(&sm->zz[hs][j * 4]);
                    ffma2_(a0, w2, hv.x);
                    ffma2_(a1, w2, hv.y);
                    ffma2_(b0, q2, zv.x);
                    ffma2_(b1, q2, zv.y);
                }
            }
            const float g = g_g1[m][i], be = g_be1[m][i];
            float v0, v1, v2, v3, u0, u1, u2, u3, h;
            unpack2_(a0, v0, v1);
            unpack2_(a1, v2, v3);
            unpack2_(b0, u0, u1);
            unpack2_(b1, u2, u3);
            float4 hv;
            float vdiv[4];
            h = tanhf_(g * v0 + be); hv.x = h; vdiv[0] = g * (1.0f - h * h) * u0;
            h = tanhf_(g * v1 + be); hv.y = h; vdiv[1] = g * (1.0f - h * h) * u1;
            h = tanhf_(g * v2 + be); hv.z = h; vdiv[2] = g * (1.0f - h * h) * u2;
            h = tanhf_(g * v3 + be); hv.w = h; vdiv[3] = g * (1.0f - h * h) * u3;
            *reinterpret_cast<float4*>(&sm->h2[hs][i * 4]) = hv;
#pragma unroll
            for (int c = 0; c < 4; c++) {
                float r = vdiv[c];
                r += __shfl_xor_sync(0xffffffffu, r, 16);
                r += __shfl_xor_sync(0xffffffffu, r, 8);
                r += __shfl_xor_sync(0xffffffffu, r, 4);
                r += __shfl_xor_sync(0xffffffffu, r, 2);
                r += __shfl_xor_sync(0xffffffffu, r, 1);
                if (lane == 0) sm->wred[wrp][c] = r;
            }
        }
        __syncthreads();

        // ----- layer 2 (128->16) + state update + next-stage input ---------
        {
            const int p = tid >> 1;          // (k,s) pair, 256 of them
            const int half = tid & 1;        // even/odd i2 split
            const int k = p & 15;
            const int s = p >> 4;
            const float* h2row = &sm->h2[s >> 2][s & 3];
            float fa = 0.0f;
#pragma unroll 8
            for (int n = 0; n < WID / 2; n++) {
                int i2 = 2 * n + half;
                fa += sm->Wt2[i2][k] * h2row[i2 * 4];
            }
            fa += __shfl_xor_sync(0xffffffffu, fa, 1);
            if (half == 0) {
                float f = g_g2[m][k] * fa + g_be2[m][k];
                float yav = sm->ya[k][s] + wst * f;
                if (st < 3) {
                    sm->ya[k][s] = yav;
                    float cn = (st == 2) ? dt : 0.5f * dt;
                    sm->x[s >> 2][k * 4 + (s & 3)] = sm->yb[k][s] + cn * f;
                } else {
                    float ybv = sm->yb[k][s] + dt6 * yav;
                    sm->yb[k][s] = ybv;
                    sm->ya[k][s] = 0.0f;
                    sm->x[s >> 2][k * 4 + (s & 3)] = ybv;
                }
            }
            if (tid < SPB) {
                const int sb = (tid >> 2) * 4, c = tid & 3;
                float dv = sm->wred[sb + 0][c] + sm->wred[sb + 1][c] +
                           sm->wred[sb + 2][c] + sm->wred[sb + 3][c];
                sm->dlp[tid] += dt6 * wst * dv;
            }
        }
        __syncthreads();
    }

    // out = delta_logp + sum(-0.5 y^2 - 0.5 log(2pi))
    if (tid < SPB) {
        const int s = tid;
        float o = sm->dlp[s];
#pragma unroll
        for (int l = 0; l < LDIM; l++) {
            float yv = sm->yb[l][s];
            o += -0.5f * yv * yv - 0.5f * LOG2PI_F;
        }
        out[s0 + s] = o;
    }
}

// ---------------------------------------------------------------------------
extern "C" void kernel_launch(void* const* d_in, const int* in_sizes, int n_in,
                              void* d_out, int out_size)
{
    (void)in_sizes; (void)n_in; (void)out_size;
    const float* W1_0 = (const float*)d_in[0];
    const float* b1_0 = (const float*)d_in[1];
    const float* W2_0 = (const float*)d_in[2];
    const float* b2_0 = (const float*)d_in[3];
    const float* W3_0 = (const float*)d_in[4];
    const float* W1_1 = (const float*)d_in[5];
    const float* b1_1 = (const float*)d_in[6];
    const float* W2_1 = (const float*)d_in[7];
    const float* b2_1 = (const float*)d_in[8];
    const float* W3_1 = (const float*)d_in[9];
    const float* W1_2 = (const float*)d_in[10];
    const float* b1_2 = (const float*)d_in[11];
    const float* W2_2 = (const float*)d_in[12];
    const float* b2_2 = (const float*)d_in[13];
    const float* W3_2 = (const float*)d_in[14];
    const float* z    = (const float*)d_in[15];
    const float* cnd  = (const float*)d_in[16];
    float* out = (float*)d_out;

    cudaFuncSetAttribute(cnf_kernel, cudaFuncAttributeMaxDynamicSharedMemorySize,
                         (int)sizeof(SM));

    prep_kernel<<<NT, WID>>>(W1_0, b1_0, W2_0, b2_0, W3_0,
                             W1_1, b1_1, W2_1, b2_1, W3_1,
                             W1_2, b1_2, W2_2, b2_2, W3_2);

    cnf_kernel<<<BATCH / SPB, NTH, sizeof(SM)>>>(z, cnd, W1_0, W1_2, out);
}

// round 6
// speedup vs baseline: 1.2923x; 1.0033x over previous
#include <cuda_runtime.h>

#define LDIM 16
#define CDIM 16
#define WID 128
#define BATCH 2048
#define NSTEPS 8
#define NT 17            // distinct t values: 1 - k/16, k=0..16
#define SPB 16           // samples per block
#define NTH 512
#define LOG2PI_F 1.8378770664093453f

typedef unsigned long long u64;

// Precomputed per-t tables (prep kernel fills these every launch)
// g_WE[m][j][i] = ( W1_1[i][j],  E_m[j][i] = W1_1[i][j] * P_m[j][i] )
// P_m[j][i] = sum_k W1_0[j][k] * g2_m[k] * W1_2[k][i]
__device__ float2 g_WE[NT][WID][WID];
__device__ float g_g0[NT][WID], g_be0[NT][WID];
__device__ float g_g1[NT][WID], g_be1[NT][WID];
__device__ float g_g2[NT][LDIM], g_be2[NT][LDIM];

__device__ __forceinline__ float sigmoidf_(float x) {
    return __fdividef(1.0f, 1.0f + __expf(-x));
}
__device__ __forceinline__ float tanhf_(float x) {
    return 1.0f - __fdividef(2.0f, __expf(2.0f * x) + 1.0f);
}
__device__ __forceinline__ u64 pack2_(float lo, float hi) {
    u64 r; asm("mov.b64 %0, {%1, %2};" : "=l"(r) : "f"(lo), "f"(hi)); return r;
}
__device__ __forceinline__ void unpack2_(u64 v, float& lo, float& hi) {
    asm("mov.b64 {%0, %1}, %2;" : "=f"(lo), "=f"(hi) : "l"(v));
}
__device__ __forceinline__ void ffma2_(u64& d, u64 a, u64 b) {
    asm("fma.rn.f32x2 %0, %1, %2, %0;" : "+l"(d) : "l"(a), "l"(b));
}

// ---------------------------------------------------------------------------
// Setup kernel
// ---------------------------------------------------------------------------
__global__ void prep_kernel(
    const float* __restrict__ W1_0, const float* __restrict__ b1_0,
    const float* __restrict__ W2_0, const float* __restrict__ b2_0,
    const float* __restrict__ W3_0,
    const float* __restrict__ W1_1, const float* __restrict__ b1_1,
    const float* __restrict__ W2_1, const float* __restrict__ b2_1,
    const float* __restrict__ W3_1,
    const float* __restrict__ W1_2, const float* __restrict__ b1_2,
    const float* __restrict__ W2_2, const float* __restrict__ b2_2,
    const float* __restrict__ W3_2)
{
    const int m = blockIdx.x;
    const int i = threadIdx.x;
    const float t = 1.0f - 0.0625f * (float)m;

    __shared__ float sg2[LDIM];

    {
        float g = sigmoidf_(W2_0[i] * t + b2_0[i]);
        g_g0[m][i] = g;
        g_be0[m][i] = g * b1_0[i] + t * W3_0[i];

        float h = sigmoidf_(W2_1[i] * t + b2_1[i]);
        g_g1[m][i] = h;
        g_be1[m][i] = h * b1_1[i] + t * W3_1[i];
    }
    if (i < LDIM) {
        float g = sigmoidf_(W2_2[i] * t + b2_2[i]);
        sg2[i] = g;
        g_g2[m][i] = g;
        g_be2[m][i] = g * b1_2[i] + t * W3_2[i];
    }
    __syncthreads();

    float a[LDIM];
#pragma unroll
    for (int k = 0; k < LDIM; k++) a[k] = sg2[k] * W1_2[k * WID + i];

    for (int j = 0; j < WID; j++) {
        float p = 0.0f;
#pragma unroll
        for (int k = 0; k < LDIM; k++) p += W1_0[j * (LDIM + CDIM) + k] * a[k];
        float w1 = W1_1[i * WID + j];
        g_WE[m][j][i] = make_float2(w1, w1 * p);
    }
}

// ---------------------------------------------------------------------------
// Main kernel: 512 threads, 16 samples/block, all 8 RK4 steps in-block.
// Thread = (neuron i = tid&127, sample-quarter hs = tid>>7), 4 samples each.
// Activation layout [q][neuron*4 + c], sample s = 4q + c.
// ---------------------------------------------------------------------------
struct SM {
    float Wt0y[LDIM][WID];         // Wt0y[j][i] = W1_0[i][j], y-part only
    float Wt2[WID][LDIM];          // Wt2[i][k] = W1_2[k][i]
    float x  [4][LDIM * 4];        // stage input (y part only)
    float h1 [4][WID * 4];
    float zz [4][WID * 4];         // g0 * (1 - h1^2)
    float h2 [4][WID * 4];
    float yb[LDIM][SPB + 1];
    float ya[LDIM][SPB + 1];
    float dlp[SPB];
    float wred[16][4];
};

__global__ void __launch_bounds__(NTH, 1)
cnf_kernel(const float* __restrict__ z, const float* __restrict__ cond,
           const float* __restrict__ W1_0, const float* __restrict__ W1_2,
           float* __restrict__ out)
{
    extern __shared__ float smraw[];
    SM* sm = reinterpret_cast<SM*>(smraw);
    const int tid  = threadIdx.x;
    const int lane = tid & 31;
    const int wrp  = tid >> 5;
    const int i    = tid & 127;       // neuron
    const int hs   = tid >> 7;        // sample quarter (q group)
    const int s0   = blockIdx.x * SPB;

    // --- weights into smem ---
    for (int idx = tid; idx < WID * LDIM; idx += NTH) {
        int r = idx >> 4, j = idx & 15;
        sm->Wt0y[j][r] = W1_0[r * (LDIM + CDIM) + j];
    }
    for (int idx = tid; idx < LDIM * WID; idx += NTH) {
        int k = idx >> 7, r = idx & 127;
        sm->Wt2[r][k] = W1_2[idx];
    }
    // --- per-sample state + initial stage input (t=1: x = z) ---
    if (tid < SPB * LDIM) {
        int s = tid >> 4, l = tid & 15;
        float zv = z[(s0 + s) * LDIM + l];
        sm->yb[l][s] = zv;
        sm->ya[l][s] = 0.0f;
        sm->x[s >> 2][l * 4 + (s & 3)] = zv;
    }
    if (tid < SPB) sm->dlp[tid] = 0.0f;

    // --- stage-invariant condition term for layer 0, kept in registers ---
    float cacc0 = 0.0f, cacc1 = 0.0f, cacc2 = 0.0f, cacc3 = 0.0f;
#pragma unroll 4
    for (int c = 0; c < CDIM; c++) {
        float w = __ldg(&W1_0[i * (LDIM + CDIM) + LDIM + c]);
        cacc0 += w * __ldg(&cond[(s0 + hs * 4 + 0) * CDIM + c]);
        cacc1 += w * __ldg(&cond[(s0 + hs * 4 + 1) * CDIM + c]);
        cacc2 += w * __ldg(&cond[(s0 + hs * 4 + 2) * CDIM + c]);
        cacc3 += w * __ldg(&cond[(s0 + hs * 4 + 3) * CDIM + c]);
    }
    const u64 ct0 = pack2_(cacc0, cacc1);
    const u64 ct1 = pack2_(cacc2, cacc3);
    __syncthreads();

    const float dt  = -0.125f;
    const float dt6 = dt * (1.0f / 6.0f);

    for (int e = 0; e < 4 * NSTEPS; e++) {
        const int step = e >> 2, st = e & 3;
        const int   m   = 2 * step + ((st == 0) ? 0 : ((st == 3) ? 2 : 1));
        const float wst = (st == 1 || st == 2) ? 2.0f : 1.0f;

        // ----- layer 0: 16 y-cols (+ cached cond term), 4 samples/thread ---
        {
            u64 a0 = ct0, a1 = ct1;
#pragma unroll
            for (int j = 0; j < LDIM; j++) {
                float w = sm->Wt0y[j][i];
                u64 w2 = pack2_(w, w);
                const ulonglong2 xv =
                    *reinterpret_cast<const ulonglong2*>(&sm->x[hs][j * 4]);
                ffma2_(a0, w2, xv.x);
                ffma2_(a1, w2, xv.y);
            }
            const float g = g_g0[m][i], be = g_be0[m][i];
            float v0, v1, v2, v3, h;
            unpack2_(a0, v0, v1);
            unpack2_(a1, v2, v3);
            float4 hv, zv;
            h = tanhf_(g * v0 + be); hv.x = h; zv.x = g * (1.0f - h * h);
            h = tanhf_(g * v1 + be); hv.y = h; zv.y = g * (1.0f - h * h);
            h = tanhf_(g * v2 + be); hv.z = h; zv.z = g * (1.0f - h * h);
            h = tanhf_(g * v3 + be); hv.w = h; zv.w = g * (1.0f - h * h);
            *reinterpret_cast<float4*>(&sm->h1[hs][i * 4]) = hv;
            *reinterpret_cast<float4*>(&sm->zz[hs][i * 4]) = zv;
        }
        __syncthreads();

        // ----- fused layer 1 (W acc) + divergence (E acc on z) -------------
        // software-pipelined LDG prefetch, depth 8, ping-pong buffers
        {
            u64 a0 = 0ull, a1 = 0ull, b0 = 0ull, b1 = 0ull;
            const float2* wep = &g_WE[m][0][i];
            float2 bufA[8], bufB[8];
#pragma unroll
            for (int jj = 0; jj < 8; jj++) bufA[jj] = __ldg(wep + jj * WID);
#pragma unroll 1
            for (int g4 = 0; g4 < 8; g4++) {
                const int j0 = g4 * 16;
#pragma unroll
                for (int jj = 0; jj < 8; jj++)
                    bufB[jj] = __ldg(wep + (j0 + 8 + jj) * WID);
#pragma unroll
                for (int jj = 0; jj < 8; jj++) {
                    const int j = j0 + jj;
                    u64 w2 = pack2_(bufA[jj].x, bufA[jj].x);
                    u64 q2 = pack2_(bufA[jj].y, bufA[jj].y);
                    const ulonglong2 hv =
                        *reinterpret_cast<const ulonglong2*>(&sm->h1[hs][j * 4]);
                    const ulonglong2 zv =
                        *reinterpret_cast<const ulonglong2*>(&sm->zz[hs][j * 4]);
                    ffma2_(a0, w2, hv.x);
                    ffma2_(a1, w2, hv.y);
                    ffma2_(b0, q2, zv.x);
                    ffma2_(b1, q2, zv.y);
                }
                if (g4 < 7) {
#pragma unroll
                    for (int jj = 0; jj < 8; jj++)
                        bufA[jj] = __ldg(wep + (j0 + 16 + jj) * WID);
                }
#pragma unroll
                for (int jj = 0; jj < 8; jj++) {
                    const int j = j0 + 8 + jj;
                    u64 w2 = pack2_(bufB[jj].x, bufB[jj].x);
                    u64 q2 = pack2_(bufB[jj].y, bufB[jj].y);
                    const ulonglong2 hv =
                        *reinterpret_cast<const ulonglong2*>(&sm->h1[hs][j * 4]);
                    const ulonglong2 zv =
                        *reinterpret_cast<const ulonglong2*>(&sm->zz[hs][j * 4]);
                    ffma2_(a0, w2, hv.x);
                    ffma2_(a1, w2, hv.y);
                    ffma2_(b0, q2, zv.x);
                    ffma2_(b1, q2, zv.y);
                }
            }
            const float g = g_g1[m][i], be = g_be1[m][i];
            float v0, v1, v2, v3, u0, u1, u2, u3, h;
            unpack2_(a0, v0, v1);
            unpack2_(a1, v2, v3);
            unpack2_(b0, u0, u1);
            unpack2_(b1, u2, u3);
            float4 hv;
            float vdiv[4];
            h = tanhf_(g * v0 + be); hv.x = h; vdiv[0] = g * (1.0f - h * h) * u0;
            h = tanhf_(g * v1 + be); hv.y = h; vdiv[1] = g * (1.0f - h * h) * u1;
            h = tanhf_(g * v2 + be); hv.z = h; vdiv[2] = g * (1.0f - h * h) * u2;
            h = tanhf_(g * v3 + be); hv.w = h; vdiv[3] = g * (1.0f - h * h) * u3;
            *reinterpret_cast<float4*>(&sm->h2[hs][i * 4]) = hv;
#pragma unroll
            for (int c = 0; c < 4; c++) {
                float r = vdiv[c];
                r += __shfl_xor_sync(0xffffffffu, r, 16);
                r += __shfl_xor_sync(0xffffffffu, r, 8);
                r += __shfl_xor_sync(0xffffffffu, r, 4);
                r += __shfl_xor_sync(0xffffffffu, r, 2);
                r += __shfl_xor_sync(0xffffffffu, r, 1);
                if (lane == 0) sm->wred[wrp][c] = r;
            }
        }
        __syncthreads();

        // ----- layer 2 (128->16) + state update + next-stage input ---------
        {
            const int p = tid >> 1;          // (k,s) pair, 256 of them
            const int half = tid & 1;        // even/odd i2 split
            const int k = p & 15;
            const int s = p >> 4;
            const float* h2row = &sm->h2[s >> 2][s & 3];
            float fa = 0.0f;
#pragma unroll 8
            for (int n = 0; n < WID / 2; n++) {
                int i2 = 2 * n + half;
                fa += sm->Wt2[i2][k] * h2row[i2 * 4];
            }
            fa += __shfl_xor_sync(0xffffffffu, fa, 1);
            if (half == 0) {
                float f = g_g2[m][k] * fa + g_be2[m][k];
                float yav = sm->ya[k][s] + wst * f;
                if (st < 3) {
                    sm->ya[k][s] = yav;
                    float cn = (st == 2) ? dt : 0.5f * dt;
                    sm->x[s >> 2][k * 4 + (s & 3)] = sm->yb[k][s] + cn * f;
                } else {
                    float ybv = sm->yb[k][s] + dt6 * yav;
                    sm->yb[k][s] = ybv;
                    sm->ya[k][s] = 0.0f;
                    sm->x[s >> 2][k * 4 + (s & 3)] = ybv;
                }
            }
            if (tid < SPB) {
                const int sb = (tid >> 2) * 4, c = tid & 3;
                float dv = sm->wred[sb + 0][c] + sm->wred[sb + 1][c] +
                           sm->wred[sb + 2][c] + sm->wred[sb + 3][c];
                sm->dlp[tid] += dt6 * wst * dv;
            }
        }
        __syncthreads();
    }

    // out = delta_logp + sum(-0.5 y^2 - 0.5 log(2pi))
    if (tid < SPB) {
        const int s = tid;
        float o = sm->dlp[s];
#pragma unroll
        for (int l = 0; l < LDIM; l++) {
            float yv = sm->yb[l][s];
            o += -0.5f * yv * yv - 0.5f * LOG2PI_F;
        }
        out[s0 + s] = o;
    }
}

// ---------------------------------------------------------------------------
extern "C" void kernel_launch(void* const* d_in, const int* in_sizes, int n_in,
                              void* d_out, int out_size)
{
    (void)in_sizes; (void)n_in; (void)out_size;
    const float* W1_0 = (const float*)d_in[0];
    const float* b1_0 = (const float*)d_in[1];
    const float* W2_0 = (const float*)d_in[2];
    const float* b2_0 = (const float*)d_in[3];
    const float* W3_0 = (const float*)d_in[4];
    const float* W1_1 = (const float*)d_in[5];
    const float* b1_1 = (const float*)d_in[6];
    const float* W2_1 = (const float*)d_in[7];
    const float* b2_1 = (const float*)d_in[8];
    const float* W3_1 = (const float*)d_in[9];
    const float* W1_2 = (const float*)d_in[10];
    const float* b1_2 = (const float*)d_in[11];
    const float* W2_2 = (const float*)d_in[12];
    const float* b2_2 = (const float*)d_in[13];
    const float* W3_2 = (const float*)d_in[14];
    const float* z    = (const float*)d_in[15];
    const float* cnd  = (const float*)d_in[16];
    float* out = (float*)d_out;

    cudaFuncSetAttribute(cnf_kernel, cudaFuncAttributeMaxDynamicSharedMemorySize,
                         (int)sizeof(SM));

    prep_kernel<<<NT, WID>>>(W1_0, b1_0, W2_0, b2_0, W3_0,
                             W1_1, b1_1, W2_1, b2_1, W3_1,
                             W1_2, b1_2, W2_2, b2_2, W3_2);

    cnf_kernel<<<BATCH / SPB, NTH, sizeof(SM)>>>(z, cnd, W1_0, W1_2, out);
}

// round 8
// speedup vs baseline: 1.7112x; 1.3241x over previous
#include <cuda_runtime.h>

#define LDIM 16
#define CDIM 16
#define WID 128
#define BATCH 2048
#define NSTEPS 8
#define NT 17            // distinct t values: 1 - k/16, k=0..16
#define SPB 16           // samples per block
#define NTH 512
#define LOG2PI_F 1.8378770664093453f

typedef unsigned long long u64;

// Precomputed per-t tables (prep kernel fills these every launch)
// g_WE[m][j][i] = ( W1_1[i][j],  E0_m[i][j] = W1_1[i][j]*P_m[j][i]*g0_m[j] )
// P_m[j][i] = sum_k W1_0[j][k]*g2_m[k]*W1_2[k][i]
// g_Es[m][i] = sum_j E0_m[i][j]
__device__ float2 g_WE[NT][WID][WID];
__device__ float  g_Es[NT][WID];
__device__ float g_g0[NT][WID], g_be0[NT][WID];
__device__ float g_g1[NT][WID], g_be1[NT][WID];
__device__ float g_g2[NT][LDIM], g_be2[NT][LDIM];

__device__ __forceinline__ float sigmoidf_(float x) {
    return __fdividef(1.0f, 1.0f + __expf(-x));
}
__device__ __forceinline__ float tanhf_(float x) {
    return 1.0f - __fdividef(2.0f, __expf(2.0f * x) + 1.0f);
}
__device__ __forceinline__ u64 pack2_(float lo, float hi) {
    u64 r; asm("mov.b64 %0, {%1, %2};" : "=l"(r) : "f"(lo), "f"(hi)); return r;
}
__device__ __forceinline__ void unpack2_(u64 v, float& lo, float& hi) {
    asm("mov.b64 {%0, %1}, %2;" : "=f"(lo), "=f"(hi) : "l"(v));
}
__device__ __forceinline__ void ffma2_(u64& d, u64 a, u64 b) {
    asm("fma.rn.f32x2 %0, %1, %2, %0;" : "+l"(d) : "l"(a), "l"(b));
}
__device__ __forceinline__ void fmul2_(u64& d, u64 a, u64 b) {
    asm("mul.rn.f32x2 %0, %1, %2;" : "=l"(d) : "l"(a), "l"(b));
}

// ---------------------------------------------------------------------------
// Setup kernel
// ---------------------------------------------------------------------------
__global__ void prep_kernel(
    const float* __restrict__ W1_0, const float* __restrict__ b1_0,
    const float* __restrict__ W2_0, const float* __restrict__ b2_0,
    const float* __restrict__ W3_0,
    const float* __restrict__ W1_1, const float* __restrict__ b1_1,
    const float* __restrict__ W2_1, const float* __restrict__ b2_1,
    const float* __restrict__ W3_1,
    const float* __restrict__ W1_2, const float* __restrict__ b1_2,
    const float* __restrict__ W2_2, const float* __restrict__ b2_2,
    const float* __restrict__ W3_2)
{
    const int m = blockIdx.x;
    const int i = threadIdx.x;
    const float t = 1.0f - 0.0625f * (float)m;

    __shared__ float sg0[WID], sg2[LDIM];

    {
        float g = sigmoidf_(W2_0[i] * t + b2_0[i]);
        sg0[i] = g;
        g_g0[m][i] = g;
        g_be0[m][i] = g * b1_0[i] + t * W3_0[i];

        float h = sigmoidf_(W2_1[i] * t + b2_1[i]);
        g_g1[m][i] = h;
        g_be1[m][i] = h * b1_1[i] + t * W3_1[i];
    }
    if (i < LDIM) {
        float g = sigmoidf_(W2_2[i] * t + b2_2[i]);
        sg2[i] = g;
        g_g2[m][i] = g;
        g_be2[m][i] = g * b1_2[i] + t * W3_2[i];
    }
    __syncthreads();

    float a[LDIM];
#pragma unroll
    for (int k = 0; k < LDIM; k++) a[k] = sg2[k] * W1_2[k * WID + i];

    float es = 0.0f;
    for (int j = 0; j < WID; j++) {
        float p = 0.0f;
#pragma unroll
        for (int k = 0; k < LDIM; k++) p += W1_0[j * (LDIM + CDIM) + k] * a[k];
        float w1 = W1_1[i * WID + j];
        float e0 = w1 * p * sg0[j];
        es += e0;
        g_WE[m][j][i] = make_float2(w1, e0);
    }
    g_Es[m][i] = es;
}

// ---------------------------------------------------------------------------
// Main kernel: 512 threads, 16 samples/block, all 8 RK4 steps in-block.
// Layer 1 uses split-j: warp w = (neuron block nb = w&3, j-partition jp = w>>2).
// Each thread accumulates ALL 16 samples over its 32 j's; partials are
// reduced across the 4 partitions through smem.
// Layer 0 / epilogue threads: (neuron i = tid&127, sample quarter hs = tid>>7).
// Activation layout [q][neuron*4 + c], sample s = 4q + c.
// ---------------------------------------------------------------------------
struct SM {
    float Wt0y[LDIM][WID];         // Wt0y[j][i] = W1_0[i][j], y-part only
    float Wt2[WID][LDIM];          // Wt2[i][k] = W1_2[k][i]
    float x  [4][LDIM * 4];        // stage input (y part only)
    float h1 [4][WID * 4];
    float h2 [4][WID * 4];
    u64 predA[4][8][WID];          // [jp][sample-pair][i] partial W-acc
    u64 predB[4][8][WID];          // [jp][sample-pair][i] partial E0*h^2-acc
    float yb[LDIM][SPB + 1];
    float ya[LDIM][SPB + 1];
    float dlp[SPB];
    float wred[16][4];
};

__global__ void __launch_bounds__(NTH, 1)
cnf_kernel(const float* __restrict__ z, const float* __restrict__ cond,
           const float* __restrict__ W1_0, const float* __restrict__ W1_2,
           float* __restrict__ out)
{
    extern __shared__ float smraw[];
    SM* sm = reinterpret_cast<SM*>(smraw);
    const int tid  = threadIdx.x;
    const int lane = tid & 31;
    const int wrp  = tid >> 5;
    const int i    = tid & 127;       // neuron (layer0 / epilogue mapping)
    const int hs   = tid >> 7;        // sample quarter
    const int nb   = wrp & 3;         // layer-1 neuron block
    const int jp   = wrp >> 2;        // layer-1 j partition
    const int il1  = nb * 32 + lane;  // layer-1 neuron
    const int s0   = blockIdx.x * SPB;

    // --- weights into smem ---
    for (int idx = tid; idx < WID * LDIM; idx += NTH) {
        int r = idx >> 4, j = idx & 15;
        sm->Wt0y[j][r] = W1_0[r * (LDIM + CDIM) + j];
    }
    for (int idx = tid; idx < LDIM * WID; idx += NTH) {
        int k = idx >> 7, r = idx & 127;
        sm->Wt2[r][k] = W1_2[idx];
    }
    // --- per-sample state + initial stage input (t=1: x = z) ---
    if (tid < SPB * LDIM) {
        int s = tid >> 4, l = tid & 15;
        float zv = z[(s0 + s) * LDIM + l];
        sm->yb[l][s] = zv;
        sm->ya[l][s] = 0.0f;
        sm->x[s >> 2][l * 4 + (s & 3)] = zv;
    }
    if (tid < SPB) sm->dlp[tid] = 0.0f;

    // --- stage-invariant condition term for layer 0, kept in registers ---
    float cacc0 = 0.0f, cacc1 = 0.0f, cacc2 = 0.0f, cacc3 = 0.0f;
#pragma unroll 4
    for (int c = 0; c < CDIM; c++) {
        float w = __ldg(&W1_0[i * (LDIM + CDIM) + LDIM + c]);
        cacc0 += w * __ldg(&cond[(s0 + hs * 4 + 0) * CDIM + c]);
        cacc1 += w * __ldg(&cond[(s0 + hs * 4 + 1) * CDIM + c]);
        cacc2 += w * __ldg(&cond[(s0 + hs * 4 + 2) * CDIM + c]);
        cacc3 += w * __ldg(&cond[(s0 + hs * 4 + 3) * CDIM + c]);
    }
    const u64 ct0 = pack2_(cacc0, cacc1);
    const u64 ct1 = pack2_(cacc2, cacc3);
    __syncthreads();

    const float dt  = -0.125f;
    const float dt6 = dt * (1.0f / 6.0f);

    for (int e = 0; e < 4 * NSTEPS; e++) {
        const int step = e >> 2, st = e & 3;
        const int   m   = 2 * step + ((st == 0) ? 0 : ((st == 3) ? 2 : 1));
        const float wst = (st == 1 || st == 2) ? 2.0f : 1.0f;

        // ----- layer 0: 16 y-cols (+ cached cond term), 4 samples/thread ---
        {
            u64 a0 = ct0, a1 = ct1;
#pragma unroll
            for (int j = 0; j < LDIM; j++) {
                float w = sm->Wt0y[j][i];
                u64 w2 = pack2_(w, w);
                const ulonglong2 xv =
                    *reinterpret_cast<const ulonglong2*>(&sm->x[hs][j * 4]);
                ffma2_(a0, w2, xv.x);
                ffma2_(a1, w2, xv.y);
            }
            const float g = g_g0[m][i], be = g_be0[m][i];
            float v0, v1, v2, v3, h;
            unpack2_(a0, v0, v1);
            unpack2_(a1, v2, v3);
            float4 hv;
            h = tanhf_(g * v0 + be); hv.x = h;
            h = tanhf_(g * v1 + be); hv.y = h;
            h = tanhf_(g * v2 + be); hv.z = h;
            h = tanhf_(g * v3 + be); hv.w = h;
            *reinterpret_cast<float4*>(&sm->h1[hs][i * 4]) = hv;
        }

        // prefetch first table chunk for this stage (independent of h1)
        const float2* wep = &g_WE[m][jp * 32][il1];
        float2 bufA[4], bufB[4];
#pragma unroll
        for (int jj = 0; jj < 4; jj++) bufA[jj] = __ldg(wep + jj * WID);

        __syncthreads();

        // ----- layer 1 split-j: accumulate all 16 samples over 32 j's ------
        {
            u64 a[8], b[8];
#pragma unroll
            for (int pr = 0; pr < 8; pr++) { a[pr] = 0ull; b[pr] = 0ull; }

#pragma unroll 1
            for (int g8 = 0; g8 < 4; g8++) {
                const int jb = jp * 32 + g8 * 8;
#pragma unroll
                for (int jj = 0; jj < 4; jj++)
                    bufB[jj] = __ldg(wep + (g8 * 8 + 4 + jj) * WID);
#pragma unroll
                for (int jj = 0; jj < 4; jj++) {
                    const int j = jb + jj;
                    u64 w2 = pack2_(bufA[jj].x, bufA[jj].x);
                    u64 e2 = pack2_(bufA[jj].y, bufA[jj].y);
#pragma unroll
                    for (int q = 0; q < 4; q++) {
                        const ulonglong2 hv =
                            *reinterpret_cast<const ulonglong2*>(&sm->h1[q][j * 4]);
                        ffma2_(a[2 * q + 0], w2, hv.x);
                        ffma2_(a[2 * q + 1], w2, hv.y);
                        u64 hh0, hh1;
                        fmul2_(hh0, hv.x, hv.x);
                        fmul2_(hh1, hv.y, hv.y);
                        ffma2_(b[2 * q + 0], e2, hh0);
                        ffma2_(b[2 * q + 1], e2, hh1);
                    }
                }
                if (g8 < 3) {
#pragma unroll
                    for (int jj = 0; jj < 4; jj++)
                        bufA[jj] = __ldg(wep + (g8 * 8 + 8 + jj) * WID);
                }
#pragma unroll
                for (int jj = 0; jj < 4; jj++) {
                    const int j = jb + 4 + jj;
                    u64 w2 = pack2_(bufB[jj].x, bufB[jj].x);
                    u64 e2 = pack2_(bufB[jj].y, bufB[jj].y);
#pragma unroll
                    for (int q = 0; q < 4; q++) {
                        const ulonglong2 hv =
                            *reinterpret_cast<const ulonglong2*>(&sm->h1[q][j * 4]);
                        ffma2_(a[2 * q + 0], w2, hv.x);
                        ffma2_(a[2 * q + 1], w2, hv.y);
                        u64 hh0, hh1;
                        fmul2_(hh0, hv.x, hv.x);
                        fmul2_(hh1, hv.y, hv.y);
                        ffma2_(b[2 * q + 0], e2, hh0);
                        ffma2_(b[2 * q + 1], e2, hh1);
                    }
                }
            }
            // store partials (disjoint per warp)
#pragma unroll
            for (int pr = 0; pr < 8; pr++) {
                sm->predA[jp][pr][il1] = a[pr];
                sm->predB[jp][pr][il1] = b[pr];
            }
        }
        __syncthreads();

        // ----- reduce partitions; tanh; divergence ------------------------
        {
            float av[4] = {0.0f, 0.0f, 0.0f, 0.0f};
            float bv[4] = {0.0f, 0.0f, 0.0f, 0.0f};
#pragma unroll
            for (int p = 0; p < 4; p++) {
                float x0, x1;
                unpack2_(sm->predA[p][2 * hs + 0][i], x0, x1);
                av[0] += x0; av[1] += x1;
                unpack2_(sm->predA[p][2 * hs + 1][i], x0, x1);
                av[2] += x0; av[3] += x1;
                unpack2_(sm->predB[p][2 * hs + 0][i], x0, x1);
                bv[0] += x0; bv[1] += x1;
                unpack2_(sm->predB[p][2 * hs + 1][i], x0, x1);
                bv[2] += x0; bv[3] += x1;
            }
            const float g  = g_g1[m][i], be = g_be1[m][i];
            const float es = __ldg(&g_Es[m][i]);
            float4 hvec;
            float vdiv[4];
#pragma unroll
            for (int c = 0; c < 4; c++) {
                float h = tanhf_(g * av[c] + be);
                ((float*)&hvec)[c] = h;
                vdiv[c] = g * (1.0f - h * h) * (es - bv[c]);
            }
            *reinterpret_cast<float4*>(&sm->h2[hs][i * 4]) = hvec;
#pragma unroll
            for (int c = 0; c < 4; c++) {
                float r = vdiv[c];
                r += __shfl_xor_sync(0xffffffffu, r, 16);
                r += __shfl_xor_sync(0xffffffffu, r, 8);
                r += __shfl_xor_sync(0xffffffffu, r, 4);
                r += __shfl_xor_sync(0xffffffffu, r, 2);
                r += __shfl_xor_sync(0xffffffffu, r, 1);
                if (lane == 0) sm->wred[wrp][c] = r;
            }
        }
        __syncthreads();

        // ----- layer 2 (128->16) + state update + next-stage input ---------
        {
            const int p = tid >> 1;          // (k,s) pair, 256 of them
            const int half = tid & 1;        // even/odd i2 split
            const int k = p & 15;
            const int s = p >> 4;
            const float* h2row = &sm->h2[s >> 2][s & 3];
            float fa = 0.0f;
#pragma unroll 8
            for (int n = 0; n < WID / 2; n++) {
                int i2 = 2 * n + half;
                fa += sm->Wt2[i2][k] * h2row[i2 * 4];
            }
            fa += __shfl_xor_sync(0xffffffffu, fa, 1);
            if (half == 0) {
                float f = g_g2[m][k] * fa + g_be2[m][k];
                float yav = sm->ya[k][s] + wst * f;
                if (st < 3) {
                    sm->ya[k][s] = yav;
                    float cn = (st == 2) ? dt : 0.5f * dt;
                    sm->x[s >> 2][k * 4 + (s & 3)] = sm->yb[k][s] + cn * f;
                } else {
                    float ybv = sm->yb[k][s] + dt6 * yav;
                    sm->yb[k][s] = ybv;
                    sm->ya[k][s] = 0.0f;
                    sm->x[s >> 2][k * 4 + (s & 3)] = ybv;
                }
            }
            if (tid < SPB) {
                const int sb = (tid >> 2) * 4, c = tid & 3;
                float dv = sm->wred[sb + 0][c] + sm->wred[sb + 1][c] +
                           sm->wred[sb + 2][c] + sm->wred[sb + 3][c];
                sm->dlp[tid] += dt6 * wst * dv;
            }
        }
        __syncthreads();
    }

    // out = delta_logp + sum(-0.5 y^2 - 0.5 log(2pi))
    if (tid < SPB) {
        const int s = tid;
        float o = sm->dlp[s];
#pragma unroll
        for (int l = 0; l < LDIM; l++) {
            float yv = sm->yb[l][s];
            o += -0.5f * yv * yv - 0.5f * LOG2PI_F;
        }
        out[s0 + s] = o;
    }
}

// ---------------------------------------------------------------------------
extern "C" void kernel_launch(void* const* d_in, const int* in_sizes, int n_in,
                              void* d_out, int out_size)
{
    (void)in_sizes; (void)n_in; (void)out_size;
    const float* W1_0 = (const float*)d_in[0];
    const float* b1_0 = (const float*)d_in[1];
    const float* W2_0 = (const float*)d_in[2];
    const float* b2_0 = (const float*)d_in[3];
    const float* W3_0 = (const float*)d_in[4];
    const float* W1_1 = (const float*)d_in[5];
    const float* b1_1 = (const float*)d_in[6];
    const float* W2_1 = (const float*)d_in[7];
    const float* b2_1 = (const float*)d_in[8];
    const float* W3_1 = (const float*)d_in[9];
    const float* W1_2 = (const float*)d_in[10];
    const float* b1_2 = (const float*)d_in[11];
    const float* W2_2 = (const float*)d_in[12];
    const float* b2_2 = (const float*)d_in[13];
    const float* W3_2 = (const float*)d_in[14];
    const float* z    = (const float*)d_in[15];
    const float* cnd  = (const float*)d_in[16];
    float* out = (float*)d_out;

    cudaFuncSetAttribute(cnf_kernel, cudaFuncAttributeMaxDynamicSharedMemorySize,
                         (int)sizeof(SM));

    prep_kernel<<<NT, WID>>>(W1_0, b1_0, W2_0, b2_0, W3_0,
                             W1_1, b1_1, W2_1, b2_1, W3_1,
                             W1_2, b1_2, W2_2, b2_2, W3_2);

    cnf_kernel<<<BATCH / SPB, NTH, sizeof(SM)>>>(z, cnd, W1_0, W1_2, out);
}